// round 11
// baseline (speedup 1.0000x reference)
#include <cuda_runtime.h>
#include <cstdint>

// ----------------------------------------------------------------------------
// ProposalLayer (RPN): decode anchors -> top-6000 (stable) -> greedy NMS -> 300
// H=128, W=192, A=9, STRIDE=16, PRE_NMS=6000, POST_NMS=300, THRESH=0.7
// 7 graph nodes, all individually bench-proven components:
//   reset, decode(+hist16), pick16, compact, rank_scatter(+gather),
//   nms_mask (bitmask matrix), nms_scan (word-skipping, register remv).
// No kernel uses more than ~16KB shared memory.
// ----------------------------------------------------------------------------

#define HH 128
#define WW 192
#define HWSZ (HH * WW)          // 24576
#define NA 9
#define NTOT (NA * HWSZ)        // 221184
#define PRE_NMS 6000
#define POST_NMS 300
#define SEL_CAP 12288
#define COLB 94                 // ceil(6000/64)

typedef unsigned long long u64;
typedef unsigned int u32;

// Anchor widths/heights (x2-x1+1); all anchor centers are at (8,8) + 16*(w,h).
__constant__ float c_aw[NA] = {184.f, 368.f, 736.f, 128.f, 256.f, 512.f, 88.f, 176.f, 352.f};
__constant__ float c_ah[NA] = {96.f, 192.f, 384.f, 128.f, 256.f, 512.f, 176.f, 352.f, 704.f};

// ------------------------------- device state -------------------------------
__device__ float4 g_boxes[NTOT];                 // decoded boxes (ref ordering)
__device__ u32 g_scf[NTOT];                      // order-preserving score keys
__device__ u64 g_sel[SEL_CAP];                   // selected keys (unsorted)
__device__ int g_selcnt;
__device__ u32 g_hist16[65536];
__device__ u32 g_thresh;
__device__ float4 g_tboxes[PRE_NMS];             // top-6000 boxes, sorted order
__device__ u64 g_vbits[COLB];                    // validity bitmask of top-6000
__device__ u64 g_mask[(size_t)PRE_NMS * COLB];   // suppression bits (j > i only)

// ------------------------------- kernels ------------------------------------

__global__ void reset_kernel() {
    int i = blockIdx.x * 1024 + threadIdx.x;     // 65536 threads
    g_hist16[i] = 0u;
    if (i < COLB) g_vbits[i] = 0ull;
    if (i == 0) { g_selcnt = 0; g_thresh = 0u; }
}

// Decode boxes + build score keys + 16-bit-bucket global histogram.
__global__ void decode_kernel(const float* __restrict__ scores,
                              const float* __restrict__ deltas,
                              const float* __restrict__ iminfo) {
    int t = blockIdx.x * blockDim.x + threadIdx.x;
    if (t >= NTOT) return;
    int a = t / HWSZ;
    int pix = t - a * HWSZ;
    int wi = pix % WW;
    int hi = pix / WW;

    float sc = scores[(NA + a) * HWSZ + pix];
    float dx = deltas[(4 * a + 0) * HWSZ + pix];
    float dy = deltas[(4 * a + 1) * HWSZ + pix];
    float dw = deltas[(4 * a + 2) * HWSZ + pix];
    float dh = deltas[(4 * a + 3) * HWSZ + pix];
    dw = fminf(fmaxf(dw, -10.f), 10.f);
    dh = fminf(fmaxf(dh, -10.f), 10.f);

    float AW = c_aw[a], AH = c_ah[a];
    float cx = dx * AW + (8.f + 16.f * (float)wi);
    float cy = dy * AH + (8.f + 16.f * (float)hi);
    float pw = __expf(dw) * AW;
    float ph = __expf(dh) * AH;
    float x1 = cx - 0.5f * pw, x2 = cx + 0.5f * pw;
    float y1 = cy - 0.5f * ph, y2 = cy + 0.5f * ph;

    float maxx = iminfo[1] - 1.0f;
    float maxy = iminfo[0] - 1.0f;
    x1 = fminf(fmaxf(x1, 0.f), maxx);
    x2 = fminf(fmaxf(x2, 0.f), maxx);
    y1 = fminf(fmaxf(y1, 0.f), maxy);
    y2 = fminf(fmaxf(y2, 0.f), maxy);

    float minsz = 16.f * iminfo[2];
    bool valid = (x2 - x1 + 1.0f >= minsz) && (y2 - y1 + 1.0f >= minsz);

    int i = pix * NA + a;  // reference flat ordering: ((h*W+w)*A + a)
    g_boxes[i] = make_float4(x1, y1, x2, y2);

    u32 u;
    if (valid) {
        u = __float_as_uint(sc);
        u = (u & 0x80000000u) ? ~u : (u | 0x80000000u);
    } else {
        u = 0x007FFFFFu;  // flip(-inf)
    }
    g_scf[i] = u;
    atomicAdd(&g_hist16[u >> 16], 1u);
}

// Pick 16-bit threshold from 65536-bin histogram. One block, 1024 threads.
__global__ void pick16_kernel() {
    __shared__ u32 ssum[1024];
    int t = threadIdx.x;
    int hi = 65535 - (t << 6);  // descending chunk of 64 bins
    u32 s = 0;
    #pragma unroll 8
    for (int k = 0; k < 64; k++) s += g_hist16[hi - k];
    ssum[t] = s;
    __syncthreads();
    for (int off = 1; off < 1024; off <<= 1) {
        u32 add = (t >= off) ? ssum[t - off] : 0u;
        __syncthreads();
        ssum[t] += add;
        __syncthreads();
    }
    u32 incl = ssum[t];
    u32 before = (t > 0) ? ssum[t - 1] : 0u;
    if (before < (u32)PRE_NMS && incl >= (u32)PRE_NMS) {
        u32 c = before;
        for (int k = 0; k < 64; k++) {
            u32 hb = g_hist16[hi - k];
            if (c + hb >= (u32)PRE_NMS) { g_thresh = (u32)(hi - k) << 16; break; }
            c += hb;
        }
    }
}

__global__ void compact_kernel() {
    int i = blockIdx.x * blockDim.x + threadIdx.x;
    if (i >= NTOT) return;
    u32 v = g_scf[i];
    if (v >= g_thresh) {
        int p = atomicAdd(&g_selcnt, 1);
        if (p < SEL_CAP)
            g_sel[p] = ((u64)v << 32) | (u32)(~(u32)i);
    }
}

// Rank-and-scatter: rank(p) = #{keys > key(p)} (keys unique: ~idx embedded,
// lower idx wins ties like jax top_k). Scatters top-6000 boxes into sorted
// order and builds the validity bitmask.
__global__ void rank_scatter_kernel() {
    __shared__ u64 tile[2048];
    int cnt = g_selcnt;
    if (cnt > SEL_CAP) cnt = SEL_CAP;
    int p = blockIdx.x * 256 + threadIdx.x;
    u64 mykey = (p < cnt) ? g_sel[p] : 0ull;
    int rank = 0;
    for (int base = 0; base < cnt; base += 2048) {
        int m = min(2048, cnt - base);
        __syncthreads();
        for (int i = threadIdx.x; i < m; i += 256) tile[i] = g_sel[base + i];
        __syncthreads();
        if (p < cnt) {
            int i = 0;
            for (; i + 4 <= m; i += 4) {
                rank += (tile[i] > mykey) + (tile[i+1] > mykey)
                      + (tile[i+2] > mykey) + (tile[i+3] > mykey);
            }
            for (; i < m; i++) rank += (tile[i] > mykey);
        }
    }
    if (p < cnt && rank < PRE_NMS) {
        u32 idx = ~(u32)mykey;
        g_tboxes[rank] = g_boxes[idx];
        if ((u32)(mykey >> 32) >= 0x80000000u)
            atomicOr(&g_vbits[rank >> 6], 1ull << (rank & 63));
    }
}

// Suppression mask: row i, bit b of word cb says box j=cb*64+b (j>i) has
// IoU(i,j) > 0.7. Upper-triangular blocks only; lower stays zero (never written).
__global__ void nms_mask_kernel() {
    int rb = blockIdx.x, cb = blockIdx.y;
    if (cb < rb) return;
    __shared__ float4 cbox[64];
    __shared__ float carea[64];
    int t = threadIdx.x;
    int j0 = cb * 64;
    float4 bj0 = (j0 + t < PRE_NMS) ? g_tboxes[j0 + t] : make_float4(0.f, 0.f, 0.f, 0.f);
    cbox[t] = bj0;
    carea[t] = (bj0.z - bj0.x) * (bj0.w - bj0.y);
    __syncthreads();
    int i = rb * 64 + t;
    if (i >= PRE_NMS) return;
    float4 bi = g_tboxes[i];
    float ai = (bi.z - bi.x) * (bi.w - bi.y);
    u64 bits = 0ull;
    int jmax = min(64, PRE_NMS - j0);
    #pragma unroll 4
    for (int b = 0; b < jmax; b++) {
        int j = j0 + b;
        if (j <= i) continue;
        float4 bj = cbox[b];
        float xx1 = fmaxf(bi.x, bj.x), yy1 = fmaxf(bi.y, bj.y);
        float xx2 = fminf(bi.z, bj.z), yy2 = fminf(bi.w, bj.w);
        float w = fmaxf(xx2 - xx1, 0.f);
        float h = fmaxf(yy2 - yy1, 0.f);
        float inter = w * h;
        float iou = inter / (ai + carea[b] - inter);
        if (iou > 0.7f) bits |= (1ull << b);
    }
    g_mask[(size_t)i * COLB + cb] = bits;
}

// Greedy scan, single warp, word-skipping: only KEPT boxes cost a mask-row
// load (~300 rows x 752B from L2). remv lives in registers (3 u64/lane);
// current word's suppression is replicated in all lanes (each lane also loads
// row[w]) so the per-kept chain is load -> OR -> ffs with no shfl. Depth-1
// speculative prefetch of the next candidate's row overlaps L2 latency.
// Early exit at 300 kept. (Bench-proven in R2/R3.)
__global__ void nms_scan_kernel(float* __restrict__ out) {
    const unsigned FULL = 0xFFFFFFFFu;
    int lane = threadIdx.x;
    for (int t = lane; t < POST_NMS * 5; t += 32) out[t] = 0.0f;

    __shared__ u64 sv[COLB];
    for (int t = lane; t < COLB; t += 32) sv[t] = g_vbits[t];
    __syncwarp();

    u64 r0 = 0ull, r1 = 0ull, r2 = 0ull;   // remv distributed: lane holds words lane, lane+32, lane+64
    int kept = 0;
    for (int w = 0; w < COLB; w++) {
        int src = w & 31;
        u64 rw = __shfl_sync(FULL, (w < 32) ? r0 : ((w < 64) ? r1 : r2), src);
        u64 cand = sv[w] & ~rw;
        int pb = -1;
        u64 p0 = 0, p1 = 0, p2 = 0, pw = 0;
        while (cand) {
            int b = __ffsll(cand) - 1;
            int i = (w << 6) + b;
            if (lane < 5) {
                float4 bx = g_tboxes[i];
                float val = (lane == 0) ? 0.f :
                            (lane == 1) ? bx.x :
                            (lane == 2) ? bx.y :
                            (lane == 3) ? bx.z : bx.w;
                out[kept * 5 + lane] = val;
            }
            kept++;
            if (kept == POST_NMS) return;

            u64 q0, q1, q2, qw;
            if (b == pb) {                  // speculation hit: row already in regs
                q0 = p0; q1 = p1; q2 = p2; qw = pw;
            } else {
                const u64* row = g_mask + (size_t)i * COLB;
                q0 = row[lane];
                q1 = (lane + 32 < COLB) ? row[lane + 32] : 0ull;
                q2 = (lane + 64 < COLB) ? row[lane + 64] : 0ull;
                qw = row[w];
            }
            // speculative prefetch of the next (pre-update) candidate's row
            u64 cnext = cand & (cand - 1);
            if (cnext) {
                int nb = __ffsll(cnext) - 1;
                const u64* nrow = g_mask + (size_t)((w << 6) + nb) * COLB;
                pb = nb;
                p0 = nrow[lane];
                p1 = (lane + 32 < COLB) ? nrow[lane + 32] : 0ull;
                p2 = (lane + 64 < COLB) ? nrow[lane + 64] : 0ull;
                pw = nrow[w];
            } else {
                pb = -1;
            }
            r0 |= q0; r1 |= q1; r2 |= q2;
            rw |= qw;                       // every lane tracks word w locally
            cand = cnext & ~rw;
        }
    }
}

// ------------------------------- launch -------------------------------------
extern "C" void kernel_launch(void* const* d_in, const int* in_sizes, int n_in,
                              void* d_out, int out_size) {
    const float* scores = (const float*)d_in[0];
    const float* deltas = (const float*)d_in[1];
    const float* iminfo = (const float*)d_in[2];
    float* out = (float*)d_out;

    reset_kernel<<<64, 1024>>>();
    decode_kernel<<<(NTOT + 255) / 256, 256>>>(scores, deltas, iminfo);
    pick16_kernel<<<1, 1024>>>();
    compact_kernel<<<(NTOT + 255) / 256, 256>>>();
    rank_scatter_kernel<<<SEL_CAP / 256, 256>>>();
    dim3 mg(COLB, COLB);
    nms_mask_kernel<<<mg, 64>>>();
    nms_scan_kernel<<<1, 32>>>(out);
}

// round 16
// speedup vs baseline: 2.3157x; 2.3157x over previous
#include <cuda_runtime.h>
#include <cstdint>

// ----------------------------------------------------------------------------
// ProposalLayer (RPN): decode anchors -> top-6000 (stable) -> greedy NMS -> 300
// H=128, W=192, A=9, STRIDE=16, PRE_NMS=6000, POST_NMS=300, THRESH=0.7
// 6 graph nodes: reset, decode(+hist16), pick16, compact, rank_scatter(+gather),
// chunked greedy NMS (no mask matrix, ~8KB static smem).
// ----------------------------------------------------------------------------

#define HH 128
#define WW 192
#define HWSZ (HH * WW)          // 24576
#define NA 9
#define NTOT (NA * HWSZ)        // 221184
#define PRE_NMS 6000
#define POST_NMS 300
#define SEL_CAP 12288
#define COLB 94                 // ceil(6000/64)

typedef unsigned long long u64;
typedef unsigned int u32;

// Anchor widths/heights (x2-x1+1); all anchor centers are at (8,8) + 16*(w,h).
__constant__ float c_aw[NA] = {184.f, 368.f, 736.f, 128.f, 256.f, 512.f, 88.f, 176.f, 352.f};
__constant__ float c_ah[NA] = {96.f, 192.f, 384.f, 128.f, 256.f, 512.f, 176.f, 352.f, 704.f};

// ------------------------------- device state -------------------------------
__device__ float4 g_boxes[NTOT];                 // decoded boxes (ref ordering)
__device__ u32 g_scf[NTOT];                      // order-preserving score keys
__device__ u64 g_sel[SEL_CAP];                   // selected keys (unsorted)
__device__ int g_selcnt;
__device__ u32 g_hist16[65536];
__device__ u32 g_thresh;
__device__ float4 g_tboxes[PRE_NMS];             // top-6000 boxes, sorted order
__device__ u64 g_vbits[COLB];                    // validity bitmask of top-6000

// ------------------------------- kernels ------------------------------------

__global__ void reset_kernel() {
    int i = blockIdx.x * 1024 + threadIdx.x;     // 65536 threads
    g_hist16[i] = 0u;
    if (i < COLB) g_vbits[i] = 0ull;
    if (i == 0) { g_selcnt = 0; g_thresh = 0u; }
}

// Decode boxes + build score keys + 16-bit-bucket global histogram.
__global__ void decode_kernel(const float* __restrict__ scores,
                              const float* __restrict__ deltas,
                              const float* __restrict__ iminfo) {
    int t = blockIdx.x * blockDim.x + threadIdx.x;
    if (t >= NTOT) return;
    int a = t / HWSZ;
    int pix = t - a * HWSZ;
    int wi = pix % WW;
    int hi = pix / WW;

    float sc = scores[(NA + a) * HWSZ + pix];
    float dx = deltas[(4 * a + 0) * HWSZ + pix];
    float dy = deltas[(4 * a + 1) * HWSZ + pix];
    float dw = deltas[(4 * a + 2) * HWSZ + pix];
    float dh = deltas[(4 * a + 3) * HWSZ + pix];
    dw = fminf(fmaxf(dw, -10.f), 10.f);
    dh = fminf(fmaxf(dh, -10.f), 10.f);

    float AW = c_aw[a], AH = c_ah[a];
    float cx = dx * AW + (8.f + 16.f * (float)wi);
    float cy = dy * AH + (8.f + 16.f * (float)hi);
    float pw = __expf(dw) * AW;
    float ph = __expf(dh) * AH;
    float x1 = cx - 0.5f * pw, x2 = cx + 0.5f * pw;
    float y1 = cy - 0.5f * ph, y2 = cy + 0.5f * ph;

    float maxx = iminfo[1] - 1.0f;
    float maxy = iminfo[0] - 1.0f;
    x1 = fminf(fmaxf(x1, 0.f), maxx);
    x2 = fminf(fmaxf(x2, 0.f), maxx);
    y1 = fminf(fmaxf(y1, 0.f), maxy);
    y2 = fminf(fmaxf(y2, 0.f), maxy);

    float minsz = 16.f * iminfo[2];
    bool valid = (x2 - x1 + 1.0f >= minsz) && (y2 - y1 + 1.0f >= minsz);

    int i = pix * NA + a;  // reference flat ordering: ((h*W+w)*A + a)
    g_boxes[i] = make_float4(x1, y1, x2, y2);

    u32 u;
    if (valid) {
        u = __float_as_uint(sc);
        u = (u & 0x80000000u) ? ~u : (u | 0x80000000u);
    } else {
        u = 0x007FFFFFu;  // flip(-inf)
    }
    g_scf[i] = u;
    atomicAdd(&g_hist16[u >> 16], 1u);
}

// Pick 16-bit threshold from 65536-bin histogram. One block, 1024 threads.
__global__ void pick16_kernel() {
    __shared__ u32 ssum[1024];
    int t = threadIdx.x;
    int hi = 65535 - (t << 6);  // descending chunk of 64 bins
    u32 s = 0;
    #pragma unroll 8
    for (int k = 0; k < 64; k++) s += g_hist16[hi - k];
    ssum[t] = s;
    __syncthreads();
    for (int off = 1; off < 1024; off <<= 1) {
        u32 add = (t >= off) ? ssum[t - off] : 0u;
        __syncthreads();
        ssum[t] += add;
        __syncthreads();
    }
    u32 incl = ssum[t];
    u32 before = (t > 0) ? ssum[t - 1] : 0u;
    if (before < (u32)PRE_NMS && incl >= (u32)PRE_NMS) {
        u32 c = before;
        for (int k = 0; k < 64; k++) {
            u32 hb = g_hist16[hi - k];
            if (c + hb >= (u32)PRE_NMS) { g_thresh = (u32)(hi - k) << 16; break; }
            c += hb;
        }
    }
}

__global__ void compact_kernel() {
    int i = blockIdx.x * blockDim.x + threadIdx.x;
    if (i >= NTOT) return;
    u32 v = g_scf[i];
    if (v >= g_thresh) {
        int p = atomicAdd(&g_selcnt, 1);
        if (p < SEL_CAP)
            g_sel[p] = ((u64)v << 32) | (u32)(~(u32)i);
    }
}

// Rank-and-scatter: rank(p) = #{keys > key(p)} (keys unique: ~idx embedded,
// lower idx wins ties like jax top_k). Scatters top-6000 boxes into sorted
// order and builds the validity bitmask.
__global__ void rank_scatter_kernel() {
    __shared__ u64 tile[2048];
    int cnt = g_selcnt;
    if (cnt > SEL_CAP) cnt = SEL_CAP;
    int p = blockIdx.x * 256 + threadIdx.x;
    u64 mykey = (p < cnt) ? g_sel[p] : 0ull;
    int rank = 0;
    for (int base = 0; base < cnt; base += 2048) {
        int m = min(2048, cnt - base);
        __syncthreads();
        for (int i = threadIdx.x; i < m; i += 256) tile[i] = g_sel[base + i];
        __syncthreads();
        if (p < cnt) {
            int i = 0;
            for (; i + 4 <= m; i += 4) {
                rank += (tile[i] > mykey) + (tile[i+1] > mykey)
                      + (tile[i+2] > mykey) + (tile[i+3] > mykey);
            }
            for (; i < m; i++) rank += (tile[i] > mykey);
        }
    }
    if (p < cnt && rank < PRE_NMS) {
        u32 idx = ~(u32)mykey;
        g_tboxes[rank] = g_boxes[idx];
        if ((u32)(mykey >> 32) >= 0x80000000u)
            atomicOr(&g_vbits[rank >> 6], 1ull << (rank & 63));
    }
}

__device__ __forceinline__ bool iou_gt(float4 a, float aa, float4 b, float ab) {
    float xx1 = fmaxf(a.x, b.x), yy1 = fmaxf(a.y, b.y);
    float xx2 = fminf(a.z, b.z), yy2 = fminf(a.w, b.w);
    float ww = fmaxf(xx2 - xx1, 0.f);
    float hh = fmaxf(yy2 - yy1, 0.f);
    float inter = ww * hh;
    return inter > 0.7f * (aa + ab - inter);
}

// Chunked greedy NMS, one block of 256 threads, ~8KB static smem, no mask
// matrix. Walk 94 words of 64 candidates in score order. Per word:
//  (a) 4 threads per candidate test suppression against the kept set (smem),
//  (b) 4 threads per candidate build intra-word pairwise suppression masks,
//  (c) thread 0 resolves the word serially with 64-bit ops, appending kept
//      boxes (exact greedy semantics) and writing output rows.
// Early exit at 300 kept.
__global__ void nms_chunked_kernel(float* __restrict__ out) {
    __shared__ float4 kbox[POST_NMS];
    __shared__ float karea[POST_NMS];
    __shared__ float4 cbox[64];
    __shared__ float carea[64];
    __shared__ u64 cmask[64];       // cmask[c]: bits j (same word) with IoU(c,j)>0.7
    __shared__ u64 s_supp;          // candidates suppressed by the kept set
    __shared__ int s_kept;

    int tid = threadIdx.x;
    int c = tid >> 2;               // candidate owned by this quad
    int sub = tid & 3;

    for (int t = tid; t < POST_NMS * 5; t += 256) out[t] = 0.0f;
    if (tid == 0) s_kept = 0;

    for (int w = 0; w < COLB; w++) {
        int base = w << 6;
        int nc = min(64, PRE_NMS - base);

        if (tid < 64) {
            float4 b = (tid < nc) ? g_tboxes[base + tid]
                                  : make_float4(0.f, 0.f, 0.f, 0.f);
            cbox[tid] = b;
            carea[tid] = (b.z - b.x) * (b.w - b.y);
            cmask[tid] = 0ull;
        }
        if (tid == 0) s_supp = 0ull;
        __syncthreads();

        float4 bc = cbox[c];
        float ac = carea[c];

        // (a) suppression by already-kept boxes (quad-split, early break)
        int kept = s_kept;
        bool supp = false;
        for (int k = sub; k < kept; k += 4) {
            if (iou_gt(bc, ac, kbox[k], karea[k])) { supp = true; break; }
        }
        if (supp) atomicOr(&s_supp, 1ull << c);

        // (b) intra-word pairwise masks: bits j > c suppressed by c
        u64 m = 0ull;
        for (int j = c + 1 + sub; j < nc; j += 4) {
            if (iou_gt(bc, ac, cbox[j], carea[j])) m |= 1ull << j;
        }
        if (m) atomicOr(&cmask[c], m);
        __syncthreads();

        // (c) serial resolution of this word
        if (tid == 0) {
            u64 alive = g_vbits[w] & ~s_supp;
            if (nc < 64) alive &= (1ull << nc) - 1ull;
            int kk = s_kept;
            while (alive && kk < POST_NMS) {
                int cc = __ffsll(alive) - 1;
                float4 b = cbox[cc];
                kbox[kk] = b;
                karea[kk] = carea[cc];
                float* o = out + kk * 5;
                o[0] = 0.f; o[1] = b.x; o[2] = b.y; o[3] = b.z; o[4] = b.w;
                kk++;
                alive &= ~(1ull << cc);
                alive &= ~cmask[cc];
            }
            s_kept = kk;
        }
        __syncthreads();
        if (s_kept >= POST_NMS) break;
    }
}

// ------------------------------- launch -------------------------------------
extern "C" void kernel_launch(void* const* d_in, const int* in_sizes, int n_in,
                              void* d_out, int out_size) {
    const float* scores = (const float*)d_in[0];
    const float* deltas = (const float*)d_in[1];
    const float* iminfo = (const float*)d_in[2];
    float* out = (float*)d_out;

    reset_kernel<<<64, 1024>>>();
    decode_kernel<<<(NTOT + 255) / 256, 256>>>(scores, deltas, iminfo);
    pick16_kernel<<<1, 1024>>>();
    compact_kernel<<<(NTOT + 255) / 256, 256>>>();
    rank_scatter_kernel<<<SEL_CAP / 256, 256>>>();
    nms_chunked_kernel<<<1, 256>>>(out);
}